// round 13
// baseline (speedup 1.0000x reference)
#include <cuda_runtime.h>
#include <cuda_fp16.h>
#include <cstdint>

#define BATCH 16384
#define EDIM  256
#define HDIM  1024
#define ADIM  256
#define NLAYER 8
#define STAGES 5

// ---------------- scratch (__device__ globals) -----------------------------
__device__ float  g_x [(size_t)BATCH * HDIM];   // fp32 residual stream
__device__ __half g_xr[(size_t)BATCH * HDIM];   // half GEMM A-operand copy
__device__ float  g_z [(size_t)BATCH * HDIM];   // pre-LN fp32
__device__ __half g_zh[(size_t)BATCH * HDIM];   // post-w1 half
__device__ float  g_e [(size_t)BATCH * EDIM];
__device__ __half g_a0[(size_t)BATCH * EDIM];
// half, transposed [N][K]: wt0 | wtb[8] | wt1 | wt2
#define WT0_OFF 0
#define WTB_OFF (WT0_OFF + (size_t)HDIM * EDIM)
#define WT1_OFF (WTB_OFF + (size_t)NLAYER * HDIM * HDIM)
#define WT2_OFF (WT1_OFF + (size_t)HDIM * HDIM)
__device__ __half g_wt[WT2_OFF + (size_t)EDIM * HDIM];

__device__ __forceinline__ uint32_t smem_u32(const void* p) {
    uint32_t a;
    asm("{ .reg .u64 t; cvta.to.shared.u64 t, %1; cvt.u32.u64 %0, t; }"
        : "=r"(a) : "l"(p));
    return a;
}
__device__ __forceinline__ void cp16(uint32_t dst, const void* src) {
    asm volatile("cp.async.cg.shared.global [%0], [%1], 16;" :: "r"(dst), "l"(src));
}
__device__ __forceinline__ void ldsm4(uint32_t& r0, uint32_t& r1,
                                      uint32_t& r2, uint32_t& r3, uint32_t addr) {
    asm volatile("ldmatrix.sync.aligned.m8n8.x4.shared.b16 {%0,%1,%2,%3}, [%4];"
                 : "=r"(r0), "=r"(r1), "=r"(r2), "=r"(r3) : "r"(addr));
}
#define CP_COMMIT() asm volatile("cp.async.commit_group;" ::: "memory")
#define CP_WAIT3()  asm volatile("cp.async.wait_group 3;" ::: "memory")

// ---------------------------------------------------------------------------
// fp16 MMA GEMM: C[M,N] = act( A[M,K] @ Bt[N,K]^T + bias[N] )
// CTA 128x128x32, 128 threads (4 warps @ 64x64), 2 CTAs/SM, 5-stage cp.async,
// register-level fragment double-buffering (ldsm overlapped with MMA).
// ---------------------------------------------------------------------------
#define AST 40                       // halves per smem row (conflict-free)
#define TILE_H (128 * AST)
#define GEMM_SMEM_BYTES (STAGES * 2 * TILE_H * 2)

template <int RELU, int OUTH>
__global__ __launch_bounds__(128, 2)
void gemm_h(const __half* __restrict__ A, const __half* __restrict__ Bt,
            const float* __restrict__ bias, float* __restrict__ Cf,
            __half* __restrict__ Ch, int N, int K)
{
    extern __shared__ __half sm[];
    __half* As = sm;                     // [STAGES][128][AST]
    __half* Bs = sm + STAGES * TILE_H;   // [STAGES][128][AST]
    const uint32_t sA = smem_u32(As);
    const uint32_t sB = smem_u32(Bs);

    const int tid  = threadIdx.x;
    const int warp = tid >> 5;
    const int lane = tid & 31;
    const int wm = (warp & 1) * 64;
    const int wn = (warp >> 1) * 64;
    const int g  = lane >> 2;
    const int tg = lane & 3;

    const int bm = blockIdx.y * 128;
    const int bn = blockIdx.x * 128;
    const int ns = K >> 5;

    const int a_off = (wm + (lane & 7) + ((lane >> 3) & 1) * 8) * AST
                    + (lane >> 4) * 8;
    const int b_off = (wn + (lane & 7) + (lane >> 4) * 8) * AST
                    + ((lane >> 3) & 1) * 8;

    float acc[4][8][4];
    #pragma unroll
    for (int i = 0; i < 4; i++)
        #pragma unroll
        for (int j = 0; j < 8; j++)
            #pragma unroll
            for (int r = 0; r < 4; r++) acc[i][j][r] = 0.f;

    auto load_stage = [&](int s, int buf) {
        const int k0 = s << 5;
        #pragma unroll
        for (int i = 0; i < 4; i++) {
            int f = tid + i * 128;
            int row = f >> 2, ch = f & 3;
            cp16(sA + (buf * TILE_H + row * AST + ch * 8) * 2,
                 A + (size_t)(bm + row) * K + k0 + ch * 8);
        }
        #pragma unroll
        for (int i = 0; i < 4; i++) {
            int f = tid + i * 128;
            int row = f >> 2, ch = f & 3;
            cp16(sB + (buf * TILE_H + row * AST + ch * 8) * 2,
                 Bt + (size_t)(bn + row) * K + k0 + ch * 8);
        }
    };

    uint32_t af[2][4][4], bf[2][4][4];

    auto ldfrag = [&](int buf, int kk, int slot) {
        const uint32_t abB = sA + (buf * TILE_H + a_off) * 2;
        const uint32_t bbB = sB + (buf * TILE_H + b_off) * 2;
        #pragma unroll
        for (int mi = 0; mi < 4; mi++)
            ldsm4(af[slot][mi][0], af[slot][mi][1], af[slot][mi][2],
                  af[slot][mi][3], abB + (mi * 16 * AST + kk) * 2);
        #pragma unroll
        for (int np = 0; np < 4; np++)
            ldsm4(bf[slot][np][0], bf[slot][np][1], bf[slot][np][2],
                  bf[slot][np][3], bbB + (np * 16 * AST + kk) * 2);
    };

    auto do_mma = [&](int slot) {
        #pragma unroll
        for (int mi = 0; mi < 4; mi++)
            #pragma unroll
            for (int ni = 0; ni < 8; ni++)
                asm volatile(
                    "mma.sync.aligned.m16n8k16.row.col.f32.f16.f16.f32 "
                    "{%0,%1,%2,%3},{%4,%5,%6,%7},{%8,%9},{%0,%1,%2,%3};"
                    : "+f"(acc[mi][ni][0]), "+f"(acc[mi][ni][1]),
                      "+f"(acc[mi][ni][2]), "+f"(acc[mi][ni][3])
                    : "r"(af[slot][mi][0]), "r"(af[slot][mi][1]),
                      "r"(af[slot][mi][2]), "r"(af[slot][mi][3]),
                      "r"(bf[slot][ni >> 1][(ni & 1) * 2]),
                      "r"(bf[slot][ni >> 1][(ni & 1) * 2 + 1]));
    };

    #pragma unroll
    for (int s = 0; s < STAGES - 1; s++) {
        load_stage(s, s);
        CP_COMMIT();
    }
    CP_WAIT3();
    __syncthreads();
    ldfrag(0, 0, 0);

    int buf = 0, pbuf = STAGES - 1;
    for (int s = 0; s < ns; s++) {
        if (s + STAGES - 1 < ns)
            load_stage(s + STAGES - 1, pbuf);
        CP_COMMIT();
        if (++pbuf == STAGES) pbuf = 0;

        ldfrag(buf, 16, 1);
        do_mma(0);

        CP_WAIT3();
        __syncthreads();
        int nb = buf + 1; if (nb == STAGES) nb = 0;
        if (s + 1 < ns) ldfrag(nb, 0, 0);
        do_mma(1);
        buf = nb;
    }

    #pragma unroll
    for (int mi = 0; mi < 4; mi++) {
        int r0 = bm + wm + mi * 16 + g;
        #pragma unroll
        for (int ni = 0; ni < 8; ni++) {
            int c0 = bn + wn + ni * 8 + tg * 2;
            float bv0 = bias[c0], bv1 = bias[c0 + 1];
            float v0 = acc[mi][ni][0] + bv0;
            float v1 = acc[mi][ni][1] + bv1;
            float v2 = acc[mi][ni][2] + bv0;
            float v3 = acc[mi][ni][3] + bv1;
            if (RELU) {
                v0 = fmaxf(v0, 0.f); v1 = fmaxf(v1, 0.f);
                v2 = fmaxf(v2, 0.f); v3 = fmaxf(v3, 0.f);
            }
            if (OUTH) {
                *(half2*)(Ch + (size_t)r0 * N + c0)       = __floats2half2_rn(v0, v1);
                *(half2*)(Ch + (size_t)(r0 + 8) * N + c0) = __floats2half2_rn(v2, v3);
            } else {
                *(float2*)(Cf + (size_t)r0 * N + c0)       = make_float2(v0, v1);
                *(float2*)(Cf + (size_t)(r0 + 8) * N + c0) = make_float2(v2, v3);
            }
        }
    }
}

// ---------------------------------------------------------------------------
__global__ __launch_bounds__(256)
void cvt_half(const float* __restrict__ src, __half* __restrict__ dst)
{
    const size_t i = (size_t)blockIdx.x * blockDim.x + threadIdx.x;
    float4 v = ((const float4*)src)[i];
    ((half2*)dst)[i * 2]     = __floats2half2_rn(v.x, v.y);
    ((half2*)dst)[i * 2 + 1] = __floats2half2_rn(v.z, v.w);
}

// ---------------------------------------------------------------------------
// batched transpose: 11 jobs in one launch; dst[n*K+k] = half(src[k*N+n])
// ---------------------------------------------------------------------------
#define NJOBS 11
struct TJobs {
    const float* src[NJOBS];
    __half*      dst[NJOBS];
    int          K[NJOBS];
    int          N[NJOBS];
};

__global__ __launch_bounds__(256)
void transpose_all(TJobs jobs)
{
    const int j = blockIdx.z;
    const int K = jobs.K[j], N = jobs.N[j];
    const int n0 = blockIdx.x * 32, k0 = blockIdx.y * 32;
    if (n0 >= N || k0 >= K) return;
    const float* src = jobs.src[j];
    __half* dst = jobs.dst[j];

    __shared__ float t[32][33];
    const int tx = threadIdx.x, ty = threadIdx.y;
    #pragma unroll
    for (int i = 0; i < 32; i += 8)
        t[ty + i][tx] = src[(size_t)(k0 + ty + i) * N + n0 + tx];
    __syncthreads();
    #pragma unroll
    for (int i = 0; i < 32; i += 8)
        dst[(size_t)(n0 + ty + i) * K + k0 + tx] = __float2half_rn(t[tx][ty + i]);
}

// ---------------------------------------------------------------------------
// LayerNorm (+residual), warp-per-row: no barriers, no smem.
// 8 rows per 256-thread CTA; lane holds 32 elems (8 float4) in registers.
// x = [x +] LN(z)*g + b (fp32); xr = half(x)
// ---------------------------------------------------------------------------
template <bool RES>
__global__ __launch_bounds__(256)
void ln_kernel(const float* __restrict__ z, float* __restrict__ x,
               __half* __restrict__ xr,
               const float* __restrict__ gamma, const float* __restrict__ beta)
{
    const int warp = threadIdx.x >> 5, lane = threadIdx.x & 31;
    const size_t row = (size_t)blockIdx.x * 8 + warp;

    const float4* zr = (const float4*)(z + row * HDIM);
    float4 v[8];
    float s = 0.f, ss = 0.f;
    #pragma unroll
    for (int i = 0; i < 8; i++) {
        v[i] = zr[lane + 32 * i];
        s  += v[i].x + v[i].y + v[i].z + v[i].w;
        ss += v[i].x * v[i].x + v[i].y * v[i].y
            + v[i].z * v[i].z + v[i].w * v[i].w;
    }
    #pragma unroll
    for (int o = 16; o; o >>= 1) {
        s  += __shfl_xor_sync(0xffffffffu, s, o);
        ss += __shfl_xor_sync(0xffffffffu, ss, o);
    }

    const float inv  = 1.f / (float)HDIM;
    const float mu   = s * inv;
    const float var  = ss * inv - mu * mu;
    const float rstd = rsqrtf(var + 1e-5f);

    float4* xrow = (float4*)(x + row * HDIM);
    half2*  xh   = (half2*)(xr + row * HDIM);
    #pragma unroll
    for (int i = 0; i < 8; i++) {
        const int c = lane + 32 * i;
        float4 gm = ((const float4*)gamma)[c];
        float4 bt = ((const float4*)beta)[c];
        float4 o;
        o.x = (v[i].x - mu) * rstd * gm.x + bt.x;
        o.y = (v[i].y - mu) * rstd * gm.y + bt.y;
        o.z = (v[i].z - mu) * rstd * gm.z + bt.z;
        o.w = (v[i].w - mu) * rstd * gm.w + bt.w;
        if (RES) {
            float4 xv = xrow[c];
            o.x += xv.x; o.y += xv.y; o.z += xv.z; o.w += xv.w;
        }
        xrow[c] = o;
        xh[c * 2]     = __floats2half2_rn(o.x, o.y);
        xh[c * 2 + 1] = __floats2half2_rn(o.z, o.w);
    }
}

// ---------------------------------------------------------------------------
// logits[b,a] = dot(xe[b], emb[b,a]); 8 actions per warp pass (16 streams)
// ---------------------------------------------------------------------------
__global__ __launch_bounds__(256)
void logits_kernel(const float* __restrict__ xe, const float* __restrict__ emb,
                   const int* __restrict__ idx, float* __restrict__ out)
{
    const int b = blockIdx.x;
    __shared__ float4 xs[EDIM / 4];
    const int t = threadIdx.x;
    if (t < EDIM / 4) xs[t] = ((const float4*)(xe + (size_t)b * EDIM))[t];
    __syncthreads();

    const int warp = t >> 5, lane = t & 31;
    const float4* ebase = (const float4*)(emb + (size_t)b * ADIM * EDIM);

    #pragma unroll
    for (int a0 = warp * 8; a0 < ADIM; a0 += 64) {
        float acc[8] = {0.f, 0.f, 0.f, 0.f, 0.f, 0.f, 0.f, 0.f};
        #pragma unroll
        for (int i = 0; i < 2; i++) {
            float4 xv = xs[lane + 32 * i];
            #pragma unroll
            for (int j = 0; j < 8; j++) {
                float4 v = ebase[(size_t)(a0 + j) * (EDIM / 4) + lane + 32 * i];
                acc[j] += v.x * xv.x + v.y * xv.y + v.z * xv.z + v.w * xv.w;
            }
        }
        #pragma unroll
        for (int o = 16; o; o >>= 1)
            #pragma unroll
            for (int j = 0; j < 8; j++)
                acc[j] += __shfl_xor_sync(0xffffffffu, acc[j], o);
        if (lane < 8) {
            int a = a0 + lane;
            int4 ii = ((const int4*)idx)[(size_t)b * ADIM + a];
            bool mask = (ii.x + ii.y + ii.z + ii.w) == 0;
            out[(size_t)b * ADIM + a] = mask ? __int_as_float(0xff800000)
                                             : acc[lane];
        }
    }
}

// ---------------------------------------------------------------------------
extern "C" void kernel_launch(void* const* d_in, const int* in_sizes, int n_in,
                              void* d_out, int out_size)
{
    (void)in_sizes; (void)n_in; (void)out_size;
    const float* obs   = (const float*)d_in[0];
    const float* emb   = (const float*)d_in[1];
    const int*   idx   = (const int*)d_in[2];
    const float* w0    = (const float*)d_in[3];
    const float* b0    = (const float*)d_in[4];
    const float* g0    = (const float*)d_in[5];
    const float* be0   = (const float*)d_in[6];
    const float* Wb    = (const float*)d_in[7];
    const float* bb    = (const float*)d_in[8];
    const float* gb    = (const float*)d_in[9];
    const float* betab = (const float*)d_in[10];
    const float* w1    = (const float*)d_in[11];
    const float* b1    = (const float*)d_in[12];
    const float* w2    = (const float*)d_in[13];
    const float* b2    = (const float*)d_in[14];
    float* out = (float*)d_out;

    float  *x, *z, *e;
    __half *xr, *zh, *a0, *wt;
    cudaGetSymbolAddress((void**)&x,  g_x);
    cudaGetSymbolAddress((void**)&xr, g_xr);
    cudaGetSymbolAddress((void**)&z,  g_z);
    cudaGetSymbolAddress((void**)&zh, g_zh);
    cudaGetSymbolAddress((void**)&e,  g_e);
    cudaGetSymbolAddress((void**)&a0, g_a0);
    cudaGetSymbolAddress((void**)&wt, g_wt);
    __half* wt0 = wt + WT0_OFF;
    __half* wtb = wt + WTB_OFF;
    __half* wt1 = wt + WT1_OFF;
    __half* wt2 = wt + WT2_OFF;

    cudaFuncSetAttribute(gemm_h<1, 0>, cudaFuncAttributeMaxDynamicSharedMemorySize,
                         GEMM_SMEM_BYTES);
    cudaFuncSetAttribute(gemm_h<1, 1>, cudaFuncAttributeMaxDynamicSharedMemorySize,
                         GEMM_SMEM_BYTES);
    cudaFuncSetAttribute(gemm_h<0, 0>, cudaFuncAttributeMaxDynamicSharedMemorySize,
                         GEMM_SMEM_BYTES);

    const dim3 blk(256);
    const dim3 tblk(32, 8);

    // preprocess: obs -> half; all weights -> transposed half in ONE launch
    cvt_half<<<(BATCH * EDIM) / 1024, blk>>>(obs, a0);
    {
        TJobs jobs;
        jobs.src[0] = w0;  jobs.dst[0] = wt0; jobs.K[0] = EDIM; jobs.N[0] = HDIM;
        for (int i = 0; i < NLAYER; i++) {
            jobs.src[1 + i] = Wb + (size_t)i * HDIM * HDIM;
            jobs.dst[1 + i] = wtb + (size_t)i * HDIM * HDIM;
            jobs.K[1 + i] = HDIM; jobs.N[1 + i] = HDIM;
        }
        jobs.src[9]  = w1; jobs.dst[9]  = wt1; jobs.K[9]  = HDIM; jobs.N[9]  = HDIM;
        jobs.src[10] = w2; jobs.dst[10] = wt2; jobs.K[10] = HDIM; jobs.N[10] = EDIM;
        transpose_all<<<dim3(32, 32, NJOBS), tblk>>>(jobs);
    }

    const dim3 gblk(128);
    const dim3 gridH(HDIM / 128, BATCH / 128);   // (8, 128)
    const dim3 gridE(EDIM / 128, BATCH / 128);   // (2, 128)
    const int  lnGrid = BATCH / 8;               // 2048

    gemm_h<1, 0><<<gridH, gblk, GEMM_SMEM_BYTES>>>(a0, wt0, b0, z, nullptr,
                                                   HDIM, EDIM);
    ln_kernel<false><<<lnGrid, blk>>>(z, x, xr, g0, be0);

    for (int i = 0; i < NLAYER; i++) {
        gemm_h<1, 0><<<gridH, gblk, GEMM_SMEM_BYTES>>>(
            xr, wtb + (size_t)i * HDIM * HDIM, bb + (size_t)i * HDIM, z, nullptr,
            HDIM, HDIM);
        ln_kernel<true><<<lnGrid, blk>>>(z, x, xr, gb + (size_t)i * HDIM,
                                         betab + (size_t)i * HDIM);
    }

    gemm_h<1, 1><<<gridH, gblk, GEMM_SMEM_BYTES>>>(xr, wt1, b1, nullptr, zh,
                                                   HDIM, HDIM);
    gemm_h<0, 0><<<gridE, gblk, GEMM_SMEM_BYTES>>>(zh, wt2, b2, e, nullptr,
                                                   EDIM, HDIM);

    logits_kernel<<<BATCH, blk>>>(e, emb, idx, out);
}

// round 15
// speedup vs baseline: 1.0436x; 1.0436x over previous
#include <cuda_runtime.h>
#include <cuda_fp16.h>
#include <cstdint>

#define BATCH 16384
#define EDIM  256
#define HDIM  1024
#define ADIM  256
#define NLAYER 8
#define STAGES 3

// ---------------- scratch (__device__ globals) -----------------------------
__device__ float  g_x [(size_t)BATCH * HDIM];   // fp32 residual stream
__device__ __half g_xr[(size_t)BATCH * HDIM];   // half GEMM A-operand copy
__device__ float  g_z [(size_t)BATCH * HDIM];   // pre-LN fp32
__device__ __half g_zh[(size_t)BATCH * HDIM];   // post-w1 half
__device__ float  g_e [(size_t)BATCH * EDIM];
__device__ __half g_a0[(size_t)BATCH * EDIM];
// half, transposed [N][K]: wt0 | wtb[8] | wt1 | wt2
#define WT0_OFF 0
#define WTB_OFF (WT0_OFF + (size_t)HDIM * EDIM)
#define WT1_OFF (WTB_OFF + (size_t)NLAYER * HDIM * HDIM)
#define WT2_OFF (WT1_OFF + (size_t)HDIM * HDIM)
__device__ __half g_wt[WT2_OFF + (size_t)EDIM * HDIM];

__device__ __forceinline__ uint32_t smem_u32(const void* p) {
    uint32_t a;
    asm("{ .reg .u64 t; cvta.to.shared.u64 t, %1; cvt.u32.u64 %0, t; }"
        : "=r"(a) : "l"(p));
    return a;
}
__device__ __forceinline__ void cp16(uint32_t dst, const void* src) {
    asm volatile("cp.async.cg.shared.global [%0], [%1], 16;" :: "r"(dst), "l"(src));
}
__device__ __forceinline__ void ldsm4(uint32_t& r0, uint32_t& r1,
                                      uint32_t& r2, uint32_t& r3, uint32_t addr) {
    asm volatile("ldmatrix.sync.aligned.m8n8.x4.shared.b16 {%0,%1,%2,%3}, [%4];"
                 : "=r"(r0), "=r"(r1), "=r"(r2), "=r"(r3) : "r"(addr));
}
#define CP_COMMIT() asm volatile("cp.async.commit_group;" ::: "memory")
#define CP_WAIT1()  asm volatile("cp.async.wait_group 1;" ::: "memory")

// ---------------------------------------------------------------------------
// fp16 MMA GEMM: C[M,N] = act( A[M,K] @ Bt[N,K]^T + bias[N] )
// CTA 128x128x64, 128 threads (4 warps @ 64x64), 2 CTAs/SM, 3-stage cp.async,
// register-level fragment double-buffering. AST=72 -> 144B row stride
// (16B-aligned for cp.async, conflict-free for ldsm: 36 words mod 32 = 4).
// ---------------------------------------------------------------------------
#define BK   64
#define AST  72
#define TILE_H (128 * AST)
#define GEMM_SMEM_BYTES (STAGES * 2 * TILE_H * 2)

template <int RELU, int OUTH>
__global__ __launch_bounds__(128, 2)
void gemm_h(const __half* __restrict__ A, const __half* __restrict__ Bt,
            const float* __restrict__ bias, float* __restrict__ Cf,
            __half* __restrict__ Ch, int N, int K)
{
    extern __shared__ __half sm[];
    __half* As = sm;                     // [STAGES][128][AST]
    __half* Bs = sm + STAGES * TILE_H;   // [STAGES][128][AST]
    const uint32_t sA = smem_u32(As);
    const uint32_t sB = smem_u32(Bs);

    const int tid  = threadIdx.x;
    const int warp = tid >> 5;
    const int lane = tid & 31;
    const int wm = (warp & 1) * 64;
    const int wn = (warp >> 1) * 64;
    const int g  = lane >> 2;
    const int tg = lane & 3;

    const int bm = blockIdx.y * 128;
    const int bn = blockIdx.x * 128;
    const int ns = K / BK;

    const int a_off = (wm + (lane & 7) + ((lane >> 3) & 1) * 8) * AST
                    + (lane >> 4) * 8;
    const int b_off = (wn + (lane & 7) + (lane >> 4) * 8) * AST
                    + ((lane >> 3) & 1) * 8;

    float acc[4][8][4];
    #pragma unroll
    for (int i = 0; i < 4; i++)
        #pragma unroll
        for (int j = 0; j < 8; j++)
            #pragma unroll
            for (int r = 0; r < 4; r++) acc[i][j][r] = 0.f;

    // per stage: A 128 rows x 64 halves = 1024 16B-chunks; same for B.
    // 128 threads -> 8 + 8 cp16 per thread.
    auto load_stage = [&](int s, int buf) {
        const int k0 = s * BK;
        #pragma unroll
        for (int i = 0; i < 8; i++) {
            int f = tid + i * 128;               // 0..1023
            int row = f >> 3, ch = f & 7;
            cp16(sA + (buf * TILE_H + row * AST + ch * 8) * 2,
                 A + (size_t)(bm + row) * K + k0 + ch * 8);
        }
        #pragma unroll
        for (int i = 0; i < 8; i++) {
            int f = tid + i * 128;
            int row = f >> 3, ch = f & 7;
            cp16(sB + (buf * TILE_H + row * AST + ch * 8) * 2,
                 Bt + (size_t)(bn + row) * K + k0 + ch * 8);
        }
    };

    uint32_t af[2][4][4], bf[2][4][4];

    auto ldfrag = [&](int buf, int kk, int slot) {
        const uint32_t abB = sA + (buf * TILE_H + a_off) * 2;
        const uint32_t bbB = sB + (buf * TILE_H + b_off) * 2;
        #pragma unroll
        for (int mi = 0; mi < 4; mi++)
            ldsm4(af[slot][mi][0], af[slot][mi][1], af[slot][mi][2],
                  af[slot][mi][3], abB + (mi * 16 * AST + kk) * 2);
        #pragma unroll
        for (int np = 0; np < 4; np++)
            ldsm4(bf[slot][np][0], bf[slot][np][1], bf[slot][np][2],
                  bf[slot][np][3], bbB + (np * 16 * AST + kk) * 2);
    };

    auto do_mma = [&](int slot) {
        #pragma unroll
        for (int mi = 0; mi < 4; mi++)
            #pragma unroll
            for (int ni = 0; ni < 8; ni++)
                asm volatile(
                    "mma.sync.aligned.m16n8k16.row.col.f32.f16.f16.f32 "
                    "{%0,%1,%2,%3},{%4,%5,%6,%7},{%8,%9},{%0,%1,%2,%3};"
                    : "+f"(acc[mi][ni][0]), "+f"(acc[mi][ni][1]),
                      "+f"(acc[mi][ni][2]), "+f"(acc[mi][ni][3])
                    : "r"(af[slot][mi][0]), "r"(af[slot][mi][1]),
                      "r"(af[slot][mi][2]), "r"(af[slot][mi][3]),
                      "r"(bf[slot][ni >> 1][(ni & 1) * 2]),
                      "r"(bf[slot][ni >> 1][(ni & 1) * 2 + 1]));
    };

    // prologue: stages 0,1 in flight; stage 0 resident before first compute
    load_stage(0, 0);
    CP_COMMIT();
    load_stage(1, 1);
    CP_COMMIT();
    CP_WAIT1();
    __syncthreads();
    ldfrag(0, 0, 0);

    int buf = 0;
    for (int s = 0; s < ns; s++) {
        if (s + 2 < ns) {
            int pb = buf + 2; if (pb >= STAGES) pb -= STAGES;
            load_stage(s + 2, pb);
        }
        CP_COMMIT();

        // chunks kk = 0,16,32,48; frag slots alternate
        ldfrag(buf, 16, 1);
        do_mma(0);
        ldfrag(buf, 32, 0);
        do_mma(1);
        ldfrag(buf, 48, 1);
        do_mma(0);

        CP_WAIT1();                 // next stage resident
        __syncthreads();            // current buf free for reuse
        int nb = buf + 1; if (nb == STAGES) nb = 0;
        if (s + 1 < ns) ldfrag(nb, 0, 0);
        do_mma(1);                  // kk=48 chunk
        buf = nb;
    }

    // epilogue: bias (+ReLU); fp32 or half store
    #pragma unroll
    for (int mi = 0; mi < 4; mi++) {
        int r0 = bm + wm + mi * 16 + g;
        #pragma unroll
        for (int ni = 0; ni < 8; ni++) {
            int c0 = bn + wn + ni * 8 + tg * 2;
            float bv0 = bias[c0], bv1 = bias[c0 + 1];
            float v0 = acc[mi][ni][0] + bv0;
            float v1 = acc[mi][ni][1] + bv1;
            float v2 = acc[mi][ni][2] + bv0;
            float v3 = acc[mi][ni][3] + bv1;
            if (RELU) {
                v0 = fmaxf(v0, 0.f); v1 = fmaxf(v1, 0.f);
                v2 = fmaxf(v2, 0.f); v3 = fmaxf(v3, 0.f);
            }
            if (OUTH) {
                *(half2*)(Ch + (size_t)r0 * N + c0)       = __floats2half2_rn(v0, v1);
                *(half2*)(Ch + (size_t)(r0 + 8) * N + c0) = __floats2half2_rn(v2, v3);
            } else {
                *(float2*)(Cf + (size_t)r0 * N + c0)       = make_float2(v0, v1);
                *(float2*)(Cf + (size_t)(r0 + 8) * N + c0) = make_float2(v2, v3);
            }
        }
    }
}

// ---------------------------------------------------------------------------
__global__ __launch_bounds__(256)
void cvt_half(const float* __restrict__ src, __half* __restrict__ dst)
{
    const size_t i = (size_t)blockIdx.x * blockDim.x + threadIdx.x;
    float4 v = ((const float4*)src)[i];
    ((half2*)dst)[i * 2]     = __floats2half2_rn(v.x, v.y);
    ((half2*)dst)[i * 2 + 1] = __floats2half2_rn(v.z, v.w);
}

// ---------------------------------------------------------------------------
// batched transpose: 11 jobs in one launch; dst[n*K+k] = half(src[k*N+n])
// ---------------------------------------------------------------------------
#define NJOBS 11
struct TJobs {
    const float* src[NJOBS];
    __half*      dst[NJOBS];
    int          K[NJOBS];
    int          N[NJOBS];
};

__global__ __launch_bounds__(256)
void transpose_all(TJobs jobs)
{
    const int j = blockIdx.z;
    const int K = jobs.K[j], N = jobs.N[j];
    const int n0 = blockIdx.x * 32, k0 = blockIdx.y * 32;
    if (n0 >= N || k0 >= K) return;
    const float* src = jobs.src[j];
    __half* dst = jobs.dst[j];

    __shared__ float t[32][33];
    const int tx = threadIdx.x, ty = threadIdx.y;
    #pragma unroll
    for (int i = 0; i < 32; i += 8)
        t[ty + i][tx] = src[(size_t)(k0 + ty + i) * N + n0 + tx];
    __syncthreads();
    #pragma unroll
    for (int i = 0; i < 32; i += 8)
        dst[(size_t)(n0 + ty + i) * K + k0 + tx] = __float2half_rn(t[tx][ty + i]);
}

// ---------------------------------------------------------------------------
// LayerNorm (+residual), CTA-per-row (known-good):
// x = [x +] LN(z)*g + b (fp32); xr = half(x)
// ---------------------------------------------------------------------------
template <bool RES>
__global__ __launch_bounds__(256)
void ln_kernel(const float* __restrict__ z, float* __restrict__ x,
               __half* __restrict__ xr,
               const float* __restrict__ gamma, const float* __restrict__ beta)
{
    const int row = blockIdx.x;
    const int t   = threadIdx.x;

    float4 v = ((const float4*)(z + (size_t)row * HDIM))[t];
    float s  = v.x + v.y + v.z + v.w;
    float ss = v.x * v.x + v.y * v.y + v.z * v.z + v.w * v.w;
    #pragma unroll
    for (int o = 16; o; o >>= 1) {
        s  += __shfl_xor_sync(0xffffffffu, s, o);
        ss += __shfl_xor_sync(0xffffffffu, ss, o);
    }
    __shared__ float sbuf[16];
    const int w = t >> 5, l = t & 31;
    if (l == 0) { sbuf[w] = s; sbuf[8 + w] = ss; }
    __syncthreads();
    float tot = 0.f, tot2 = 0.f;
    #pragma unroll
    for (int i = 0; i < 8; i++) { tot += sbuf[i]; tot2 += sbuf[8 + i]; }

    const float inv  = 1.f / (float)HDIM;
    const float mu   = tot * inv;
    const float var  = tot2 * inv - mu * mu;
    const float rstd = rsqrtf(var + 1e-5f);

    float4 gm = ((const float4*)gamma)[t];
    float4 bt = ((const float4*)beta)[t];
    float4 o;
    o.x = (v.x - mu) * rstd * gm.x + bt.x;
    o.y = (v.y - mu) * rstd * gm.y + bt.y;
    o.z = (v.z - mu) * rstd * gm.z + bt.z;
    o.w = (v.w - mu) * rstd * gm.w + bt.w;
    if (RES) {
        float4 xv = ((const float4*)(x + (size_t)row * HDIM))[t];
        o.x += xv.x; o.y += xv.y; o.z += xv.z; o.w += xv.w;
    }
    ((float4*)(x + (size_t)row * HDIM))[t] = o;
    ((half2*)(xr + (size_t)row * HDIM))[t * 2]     = __floats2half2_rn(o.x, o.y);
    ((half2*)(xr + (size_t)row * HDIM))[t * 2 + 1] = __floats2half2_rn(o.z, o.w);
}

// ---------------------------------------------------------------------------
// logits[b,a] = dot(xe[b], emb[b,a]); 8 actions per warp pass (16 streams)
// ---------------------------------------------------------------------------
__global__ __launch_bounds__(256)
void logits_kernel(const float* __restrict__ xe, const float* __restrict__ emb,
                   const int* __restrict__ idx, float* __restrict__ out)
{
    const int b = blockIdx.x;
    __shared__ float4 xs[EDIM / 4];
    const int t = threadIdx.x;
    if (t < EDIM / 4) xs[t] = ((const float4*)(xe + (size_t)b * EDIM))[t];
    __syncthreads();

    const int warp = t >> 5, lane = t & 31;
    const float4* ebase = (const float4*)(emb + (size_t)b * ADIM * EDIM);

    #pragma unroll
    for (int a0 = warp * 8; a0 < ADIM; a0 += 64) {
        float acc[8] = {0.f, 0.f, 0.f, 0.f, 0.f, 0.f, 0.f, 0.f};
        #pragma unroll
        for (int i = 0; i < 2; i++) {
            float4 xv = xs[lane + 32 * i];
            #pragma unroll
            for (int j = 0; j < 8; j++) {
                float4 v = ebase[(size_t)(a0 + j) * (EDIM / 4) + lane + 32 * i];
                acc[j] += v.x * xv.x + v.y * xv.y + v.z * xv.z + v.w * xv.w;
            }
        }
        #pragma unroll
        for (int o = 16; o; o >>= 1)
            #pragma unroll
            for (int j = 0; j < 8; j++)
                acc[j] += __shfl_xor_sync(0xffffffffu, acc[j], o);
        if (lane < 8) {
            int a = a0 + lane;
            int4 ii = ((const int4*)idx)[(size_t)b * ADIM + a];
            bool mask = (ii.x + ii.y + ii.z + ii.w) == 0;
            out[(size_t)b * ADIM + a] = mask ? __int_as_float(0xff800000)
                                             : acc[lane];
        }
    }
}

// ---------------------------------------------------------------------------
extern "C" void kernel_launch(void* const* d_in, const int* in_sizes, int n_in,
                              void* d_out, int out_size)
{
    (void)in_sizes; (void)n_in; (void)out_size;
    const float* obs   = (const float*)d_in[0];
    const float* emb   = (const float*)d_in[1];
    const int*   idx   = (const int*)d_in[2];
    const float* w0    = (const float*)d_in[3];
    const float* b0    = (const float*)d_in[4];
    const float* g0    = (const float*)d_in[5];
    const float* be0   = (const float*)d_in[6];
    const float* Wb    = (const float*)d_in[7];
    const float* bb    = (const float*)d_in[8];
    const float* gb    = (const float*)d_in[9];
    const float* betab = (const float*)d_in[10];
    const float* w1    = (const float*)d_in[11];
    const float* b1    = (const float*)d_in[12];
    const float* w2    = (const float*)d_in[13];
    const float* b2    = (const float*)d_in[14];
    float* out = (float*)d_out;

    float  *x, *z, *e;
    __half *xr, *zh, *a0, *wt;
    cudaGetSymbolAddress((void**)&x,  g_x);
    cudaGetSymbolAddress((void**)&xr, g_xr);
    cudaGetSymbolAddress((void**)&z,  g_z);
    cudaGetSymbolAddress((void**)&zh, g_zh);
    cudaGetSymbolAddress((void**)&e,  g_e);
    cudaGetSymbolAddress((void**)&a0, g_a0);
    cudaGetSymbolAddress((void**)&wt, g_wt);
    __half* wt0 = wt + WT0_OFF;
    __half* wtb = wt + WTB_OFF;
    __half* wt1 = wt + WT1_OFF;
    __half* wt2 = wt + WT2_OFF;

    cudaFuncSetAttribute(gemm_h<1, 0>, cudaFuncAttributeMaxDynamicSharedMemorySize,
                         GEMM_SMEM_BYTES);
    cudaFuncSetAttribute(gemm_h<1, 1>, cudaFuncAttributeMaxDynamicSharedMemorySize,
                         GEMM_SMEM_BYTES);
    cudaFuncSetAttribute(gemm_h<0, 0>, cudaFuncAttributeMaxDynamicSharedMemorySize,
                         GEMM_SMEM_BYTES);

    const dim3 blk(256);
    const dim3 tblk(32, 8);

    // preprocess: obs -> half; all weights -> transposed half in ONE launch
    cvt_half<<<(BATCH * EDIM) / 1024, blk>>>(obs, a0);
    {
        TJobs jobs;
        jobs.src[0] = w0;  jobs.dst[0] = wt0; jobs.K[0] = EDIM; jobs.N[0] = HDIM;
        for (int i = 0; i < NLAYER; i++) {
            jobs.src[1 + i] = Wb + (size_t)i * HDIM * HDIM;
            jobs.dst[1 + i] = wtb + (size_t)i * HDIM * HDIM;
            jobs.K[1 + i] = HDIM; jobs.N[1 + i] = HDIM;
        }
        jobs.src[9]  = w1; jobs.dst[9]  = wt1; jobs.K[9]  = HDIM; jobs.N[9]  = HDIM;
        jobs.src[10] = w2; jobs.dst[10] = wt2; jobs.K[10] = HDIM; jobs.N[10] = EDIM;
        transpose_all<<<dim3(32, 32, NJOBS), tblk>>>(jobs);
    }

    const dim3 gblk(128);
    const dim3 gridH(HDIM / 128, BATCH / 128);   // (8, 128)
    const dim3 gridE(EDIM / 128, BATCH / 128);   // (2, 128)

    gemm_h<1, 0><<<gridH, gblk, GEMM_SMEM_BYTES>>>(a0, wt0, b0, z, nullptr,
                                                   HDIM, EDIM);
    ln_kernel<false><<<BATCH, blk>>>(z, x, xr, g0, be0);

    for (int i = 0; i < NLAYER; i++) {
        gemm_h<1, 0><<<gridH, gblk, GEMM_SMEM_BYTES>>>(
            xr, wtb + (size_t)i * HDIM * HDIM, bb + (size_t)i * HDIM, z, nullptr,
            HDIM, HDIM);
        ln_kernel<true><<<BATCH, blk>>>(z, x, xr, gb + (size_t)i * HDIM,
                                        betab + (size_t)i * HDIM);
    }

    gemm_h<1, 1><<<gridH, gblk, GEMM_SMEM_BYTES>>>(xr, wt1, b1, nullptr, zh,
                                                   HDIM, HDIM);
    gemm_h<0, 0><<<gridE, gblk, GEMM_SMEM_BYTES>>>(zh, wt2, b2, e, nullptr,
                                                   EDIM, HDIM);

    logits_kernel<<<BATCH, blk>>>(e, emb, idx, out);
}